// round 1
// baseline (speedup 1.0000x reference)
#include <cuda_runtime.h>

// ============================================================================
// Relative-position MHA (NO softmax) — algebraically restructured.
//
//   scores = (Q Kt + Q·relK[clip]) / 16
//   w1 = scores @ V   ->  Q (K^T V)  +  banded/prefix terms with relK buckets
//   w2 = scores @ relV->  21 bucketed score row-sums (prefix + band) x relV
//   out = (w1+w2) @ W0^T + b0
// ============================================================================

#define D_MODEL 256
#define HEADS   8
#define DH      32
#define SEQ     2048
#define BATCH   2
#define MAXREL  10
#define NT      21                  // 2*MAXREL+1
#define BHN     (BATCH*HEADS)       // 16
#define MROWS   (BATCH*SEQ)         // 4096
#define CHUNK   128
#define NCHUNK  (SEQ/CHUNK)         // 16
#define QT      128
#define INV_SCALE (1.0f/16.0f)      // 1/sqrt(256)

// -------------------- scratch (device globals; no allocs) -------------------
__device__ float g_Qp[MROWS*D_MODEL];
__device__ float g_Kp[MROWS*D_MODEL];
__device__ float g_Vp[MROWS*D_MODEL];
__device__ float g_Kpre[MROWS*D_MODEL];   // within-chunk inclusive prefix of Kp
__device__ float g_Vpre[MROWS*D_MODEL];
__device__ float g_X[MROWS*D_MODEL];      // (w1+w2)/SCALE, layout [b,s,h*32+d]
__device__ float g_ctotK[BHN*NCHUNK*DH];
__device__ float g_ctotV[BHN*NCHUNK*DH];
__device__ float g_koff[BHN*(NCHUNK+1)*DH]; // exclusive chunk offsets; [16]=total
__device__ float g_voff[BHN*(NCHUNK+1)*DH];
__device__ float g_ktvp[NCHUNK*BHN*DH*DH];  // per-chunk partial K^T V
__device__ float g_ktv[BHN*DH*DH];          // K^T V per (b,h): [e][d]

// ============================================================================
// fp32 GEMM:  C[M,256] = A[M,256] @ W^T + bias      (BM=128, BN=64, BK=16)
// ============================================================================
__device__ __forceinline__ void gemm_body(const float* __restrict__ A,
                                          const float* __restrict__ W,
                                          const float* __restrict__ bias,
                                          float* __restrict__ C)
{
    __shared__ float As[16*132];
    __shared__ float Bs[16*68];
    const int tid = threadIdx.x;
    const int tm  = tid >> 4;      // 0..15 -> rows tm*8..+7
    const int tn  = tid & 15;      // 0..15 -> cols tn*4..+3
    const int m0  = blockIdx.x * 128;
    const int n0  = blockIdx.y * 64;

    float acc[8][4];
#pragma unroll
    for (int i = 0; i < 8; i++)
#pragma unroll
        for (int j = 0; j < 4; j++) acc[i][j] = 0.f;

    for (int kt = 0; kt < 256; kt += 16) {
        // A tile 128x16 (512 float4, 2/thread), stored transposed As[k][m]
#pragma unroll
        for (int r = 0; r < 2; r++) {
            int idx = tid + r*256;
            int m   = idx >> 2;
            int k4  = (idx & 3) << 2;
            const float4 av = *reinterpret_cast<const float4*>(
                &A[(size_t)(m0+m)*256 + kt + k4]);
            As[(k4+0)*132+m] = av.x;  As[(k4+1)*132+m] = av.y;
            As[(k4+2)*132+m] = av.z;  As[(k4+3)*132+m] = av.w;
        }
        // W tile: rows n0..n0+63, cols kt..kt+15, stored Bs[k][n] = W[n][k]
        {
            int n  = tid >> 2;
            int k4 = (tid & 3) << 2;
            const float4 wv = *reinterpret_cast<const float4*>(
                &W[(size_t)(n0+n)*256 + kt + k4]);
            Bs[(k4+0)*68+n] = wv.x;  Bs[(k4+1)*68+n] = wv.y;
            Bs[(k4+2)*68+n] = wv.z;  Bs[(k4+3)*68+n] = wv.w;
        }
        __syncthreads();
#pragma unroll
        for (int k = 0; k < 16; k++) {
            float a[8], bb[4];
#pragma unroll
            for (int i = 0; i < 8; i++) a[i] = As[k*132 + tm*8 + i];
#pragma unroll
            for (int j = 0; j < 4; j++) bb[j] = Bs[k*68 + tn*4 + j];
#pragma unroll
            for (int i = 0; i < 8; i++)
#pragma unroll
                for (int j = 0; j < 4; j++) acc[i][j] += a[i]*bb[j];
        }
        __syncthreads();
    }

    const float b0 = bias[n0+tn*4+0], b1 = bias[n0+tn*4+1];
    const float b2 = bias[n0+tn*4+2], b3 = bias[n0+tn*4+3];
#pragma unroll
    for (int i = 0; i < 8; i++) {
        float4 o = make_float4(acc[i][0]+b0, acc[i][1]+b1, acc[i][2]+b2, acc[i][3]+b3);
        *reinterpret_cast<float4*>(&C[(size_t)(m0+tm*8+i)*256 + n0 + tn*4]) = o;
    }
}

// Q/K/V projections fused into one launch (blockIdx.z picks which)
__global__ __launch_bounds__(256) void proj_gemm(
    const float* __restrict__ q,  const float* __restrict__ k,  const float* __restrict__ v,
    const float* __restrict__ Wq, const float* __restrict__ bq,
    const float* __restrict__ Wk, const float* __restrict__ bk,
    const float* __restrict__ Wv, const float* __restrict__ bv)
{
    const float* A; const float* W; const float* B; float* C;
    if (blockIdx.z == 0)      { A = q; W = Wq; B = bq; C = g_Qp; }
    else if (blockIdx.z == 1) { A = k; W = Wk; B = bk; C = g_Kp; }
    else                      { A = v; W = Wv; B = bv; C = g_Vp; }
    gemm_body(A, W, B, C);
}

__global__ __launch_bounds__(256) void final_gemm(
    const float* __restrict__ W0, const float* __restrict__ b0,
    float* __restrict__ out)
{
    gemm_body(g_X, W0, b0, out);
}

// ============================================================================
// Prefix scans along seq (per b,h,d):  two-level (chunk scan + offsets)
// ============================================================================
__global__ void scan_chunks()
{
    const int chunk = blockIdx.x, bh = blockIdx.y;
    const int b = bh >> 3, h = bh & 7;
    const int d = threadIdx.x; // 32 threads
    const float* src; float* dst; float* ctot;
    if (blockIdx.z == 0) { src = g_Kp; dst = g_Kpre; ctot = g_ctotK; }
    else                 { src = g_Vp; dst = g_Vpre; ctot = g_ctotV; }
    const size_t base = ((size_t)(b*SEQ + chunk*CHUNK))*D_MODEL + h*DH + d;
    float acc = 0.f;
    for (int i = 0; i < CHUNK; i += 8) {
        float t[8];
#pragma unroll
        for (int j = 0; j < 8; j++) t[j] = src[base + (size_t)(i+j)*D_MODEL];
#pragma unroll
        for (int j = 0; j < 8; j++) { acc += t[j]; dst[base + (size_t)(i+j)*D_MODEL] = acc; }
    }
    ctot[(bh*NCHUNK + chunk)*DH + d] = acc;
}

__global__ void scan_offsets()
{
    const int bh = blockIdx.x, d = threadIdx.x;
    const float* ctot = (blockIdx.y == 0) ? g_ctotK : g_ctotV;
    float*       off  = (blockIdx.y == 0) ? g_koff  : g_voff;
    float acc = 0.f;
    for (int c = 0; c < NCHUNK; c++) {
        off[(bh*(NCHUNK+1)+c)*DH + d] = acc;
        acc += ctot[(bh*NCHUNK+c)*DH + d];
    }
    off[(bh*(NCHUNK+1)+NCHUNK)*DH + d] = acc; // grand total
}

// ============================================================================
// K^T V per (b,h): chunk partials + deterministic reduce (no atomics)
// ============================================================================
__global__ __launch_bounds__(256) void ktv_partial()
{
    const int chunk = blockIdx.x, bh = blockIdx.y;
    const int b = bh >> 3, h = bh & 7;
    __shared__ float K8[8][DH], V8[8][DH];
    const int tid = threadIdx.x;
    const int e  = tid & 31;
    const int dg = tid >> 5;           // 0..7 -> d = dg*4..+3
    const int row = tid >> 5, col = tid & 31;
    float a0=0.f, a1=0.f, a2=0.f, a3=0.f;
    for (int kk = 0; kk < CHUNK; kk += 8) {
        const size_t gi = ((size_t)(b*SEQ + chunk*CHUNK + kk + row))*D_MODEL + h*DH + col;
        K8[row][col] = g_Kp[gi];
        V8[row][col] = g_Vp[gi];
        __syncthreads();
#pragma unroll
        for (int j = 0; j < 8; j++) {
            const float kv = K8[j][e];
            a0 += kv * V8[j][dg*4+0];
            a1 += kv * V8[j][dg*4+1];
            a2 += kv * V8[j][dg*4+2];
            a3 += kv * V8[j][dg*4+3];
        }
        __syncthreads();
    }
    float* p = &g_ktvp[((size_t)chunk*BHN + bh)*DH*DH + e*DH + dg*4];
    p[0]=a0; p[1]=a1; p[2]=a2; p[3]=a3;
}

__global__ void ktv_reduce()
{
    const int bh = blockIdx.x;
    for (int i = threadIdx.x; i < DH*DH; i += blockDim.x) {
        float s = 0.f;
        for (int c = 0; c < NCHUNK; c++) s += g_ktvp[((size_t)c*BHN + bh)*DH*DH + i];
        g_ktv[bh*DH*DH + i] = s;
    }
}

// ============================================================================
// Stage 3: per (b,h,q) combine — content via KtV, rel via band + prefix buckets
// ============================================================================
__global__ __launch_bounds__(256) void stage3(const float* __restrict__ tk,
                                              const float* __restrict__ tv)
{
    const int bh = blockIdx.y;
    const int b = bh >> 3, h = bh & 7;
    const int q0 = blockIdx.x * QT;

    __shared__ float Ksm[(QT+2*MAXREL)*33];   // rows q0-10 .. q0+QT+9, padded
    __shared__ float Vsm[(QT+2*MAXREL)*32];
    __shared__ float KtVs[DH*DH];             // [e][d]
    __shared__ float Tks[NT*33];
    __shared__ float Tvs[NT*32];

    const int tid = threadIdx.x;
    for (int i = tid; i < (QT+2*MAXREL)*DH; i += 256) {
        const int row = i >> 5, d = i & 31;
        const int kidx = q0 - MAXREL + row;
        float kv = 0.f, vv = 0.f;
        if (kidx >= 0 && kidx < SEQ) {
            const size_t gi = ((size_t)(b*SEQ + kidx))*D_MODEL + h*DH + d;
            kv = g_Kp[gi]; vv = g_Vp[gi];
        }
        Ksm[row*33 + d] = kv;
        Vsm[row*32 + d] = vv;
    }
    for (int i = tid; i < DH*DH; i += 256) KtVs[i] = g_ktv[bh*DH*DH + i];
    for (int i = tid; i < NT*DH; i += 256) {
        const int t = i >> 5, e = i & 31;
        Tks[t*33 + e] = tk[i];
        Tvs[i]        = tv[i];
    }
    __syncthreads();

    const int w = tid >> 5, lane = tid & 31;
    const float ktotL = g_koff[(bh*(NCHUNK+1)+NCHUNK)*DH + lane];
    const float vtotL = g_voff[(bh*(NCHUNK+1)+NCHUNK)*DH + lane];

    for (int iq = 0; iq < QT/8; iq++) {
        const int q = q0 + iq*8 + w;
        const float qreg = g_Qp[((size_t)(b*SEQ + q))*D_MODEL + h*DH + lane];

        // prefix (k <= q-10) and suffix (k >= q+10) rows, per-lane (lane = d/e)
        float kpreL = 0.f, vpreL = 0.f, ksufL = 0.f, vsufL = 0.f;
        const int r1 = q - MAXREL;
        if (r1 >= 0) {
            const size_t gi = ((size_t)(b*SEQ + r1))*D_MODEL + h*DH + lane;
            const int c = r1 >> 7;
            kpreL = g_Kpre[gi] + g_koff[(bh*(NCHUNK+1)+c)*DH + lane];
            vpreL = g_Vpre[gi] + g_voff[(bh*(NCHUNK+1)+c)*DH + lane];
        }
        const bool hasR = (q + MAXREL) <= SEQ-1;
        if (hasR) {
            const int r2 = q + MAXREL - 1;
            const size_t gi = ((size_t)(b*SEQ + r2))*D_MODEL + h*DH + lane;
            const int c = r2 >> 7;
            ksufL = ktotL - (g_Kpre[gi] + g_koff[(bh*(NCHUNK+1)+c)*DH + lane]);
            vsufL = vtotL - (g_Vpre[gi] + g_voff[(bh*(NCHUNK+1)+c)*DH + lane]);
        }

        // ---- dot phase: lane t computes s_t = qv.Tk[t] and interior qv.K[k_t]
        const int tmin = (lane < NT-1) ? lane : NT-1;
        const float* krow = &Ksm[(q - q0 + tmin)*33];
        const float* tkr  = &Tks[tmin*33];
        float acc_s = 0.f, acc_int = 0.f, acc_ktv = 0.f;
        float pp = qreg * kpreL;   // reduced below -> qv.Kpre
        float ss = qreg * ksufL;   // reduced below -> qv.Ksuf
#pragma unroll
        for (int e = 0; e < 32; e++) {
            const float qe = __shfl_sync(0xffffffffu, qreg, e);
            acc_s   += qe * tkr[e];
            acc_int += qe * krow[e];
            acc_ktv += qe * KtVs[e*DH + lane];
        }
#pragma unroll
        for (int off = 16; off > 0; off >>= 1) {
            pp += __shfl_xor_sync(0xffffffffu, pp, off);
            ss += __shfl_xor_sync(0xffffffffu, ss, off);
        }

        // ---- bucketed score row-sums S_t (raw, unscaled), one per lane t
        float Sval;
        if (lane == 0) {
            Sval = (r1 >= 0) ? (pp + (float)(q - MAXREL + 1) * acc_s) : 0.f;
        } else if (lane == NT-1) {
            Sval = hasR ? (ss + (float)(SEQ - q - MAXREL) * acc_s) : 0.f;
        } else if (lane < NT-1) {
            const int kk = q + lane - MAXREL;
            Sval = (kk >= 0 && kk < SEQ) ? (acc_int + acc_s) : 0.f;
        } else {
            Sval = 0.f;
        }

        // ---- combine (lane = output d)
        const float s0  = __shfl_sync(0xffffffffu, acc_s, 0);
        const float s20 = __shfl_sync(0xffffffffu, acc_s, NT-1);
        float wv = acc_ktv + s0*vpreL + s20*vsufL;   // vpre/vsuf are 0 if invalid
        const int base = q - q0;
#pragma unroll
        for (int t = 1; t < NT-1; t++) {
            const float st = __shfl_sync(0xffffffffu, acc_s, t);
            const int kk = q + t - MAXREL;
            if (kk >= 0 && kk < SEQ)                  // warp-uniform predicate
                wv += st * Vsm[(base+t)*32 + lane];
        }
#pragma unroll
        for (int t = 0; t < NT; t++) {
            const float sv = __shfl_sync(0xffffffffu, Sval, t);
            wv += sv * Tvs[t*32 + lane];
        }

        g_X[((size_t)(b*SEQ + q))*D_MODEL + h*DH + lane] = wv * INV_SCALE;
    }
}

// ============================================================================
// launch
// ============================================================================
extern "C" void kernel_launch(void* const* d_in, const int* in_sizes, int n_in,
                              void* d_out, int out_size)
{
    const float* q   = (const float*)d_in[0];
    const float* k   = (const float*)d_in[1];
    const float* v   = (const float*)d_in[2];
    // d_in[3] = mask (no-op in reference)
    const float* Wq  = (const float*)d_in[4];
    const float* bq  = (const float*)d_in[5];
    const float* Wk  = (const float*)d_in[6];
    const float* bk  = (const float*)d_in[7];
    const float* Wv  = (const float*)d_in[8];
    const float* bv  = (const float*)d_in[9];
    const float* W0  = (const float*)d_in[10];
    const float* b0  = (const float*)d_in[11];
    const float* tk  = (const float*)d_in[12];
    const float* tv  = (const float*)d_in[13];
    float* out = (float*)d_out;

    proj_gemm  <<<dim3(MROWS/128, D_MODEL/64, 3), 256>>>(q, k, v, Wq, bq, Wk, bk, Wv, bv);
    scan_chunks<<<dim3(NCHUNK, BHN, 2), 32>>>();
    scan_offsets<<<dim3(BHN, 2), 32>>>();
    ktv_partial<<<dim3(NCHUNK, BHN), 256>>>();
    ktv_reduce <<<BHN, 256>>>();
    stage3     <<<dim3(SEQ/QT, BHN), 256>>>(tk, tv);
    final_gemm <<<dim3(MROWS/128, D_MODEL/64), 256>>>(W0, b0, out);
}

// round 2
// speedup vs baseline: 1.1085x; 1.1085x over previous
#include <cuda_runtime.h>
#include <cuda_bf16.h>
#include <cstdint>

// ============================================================================
// Relative-position MHA (NO softmax) — algebraic restructure + bf16 split MMA.
//   proj/final GEMMs: split-bf16 (3-term) tensor-core mma.sync, K'=768
//   content path:  Q (K^T V)
//   relative path: 21-bucket band + prefix/suffix sums
// ============================================================================

#define D_MODEL 256
#define HEADS   8
#define DH      32
#define SEQ     2048
#define BATCH   2
#define MAXREL  10
#define NT      21
#define BHN     (BATCH*HEADS)       // 16
#define MROWS   (BATCH*SEQ)         // 4096
#define CHUNK   128
#define NCHUNK  (SEQ/CHUNK)         // 16
#define QT      128
#define INV_SCALE (1.0f/16.0f)
#define KTOT 768                    // split-bf16: [hi | lo | hi]
#define WSZ  (D_MODEL*KTOT)

// -------------------- scratch (device globals; no allocs) -------------------
__device__ __align__(16) __nv_bfloat16 g_A2q[MROWS*KTOT];
__device__ __align__(16) __nv_bfloat16 g_A2k[MROWS*KTOT];
__device__ __align__(16) __nv_bfloat16 g_A2v[MROWS*KTOT];
__device__ __align__(16) __nv_bfloat16 g_X2 [MROWS*KTOT];
__device__ __align__(16) __nv_bfloat16 g_B2 [4*WSZ];          // Wq,Wk,Wv,W0
__device__ float g_Qp[MROWS*D_MODEL];
__device__ float g_Kp[MROWS*D_MODEL];
__device__ float g_Vp[MROWS*D_MODEL];
__device__ float g_Kpre[MROWS*D_MODEL];
__device__ float g_Vpre[MROWS*D_MODEL];
__device__ float g_ctotK[BHN*NCHUNK*DH];
__device__ float g_ctotV[BHN*NCHUNK*DH];
__device__ float g_koff[BHN*(NCHUNK+1)*DH];
__device__ float g_voff[BHN*(NCHUNK+1)*DH];
__device__ __align__(16) float g_ktvp[128*BHN*DH*DH];         // 128 slabs
__device__ float g_ktv[BHN*DH*DH];

// ============================================================================
// split-bf16 conversion
// ============================================================================
__device__ __forceinline__ void split4(const float4 x, uint2& Hu, uint2& Lu)
{
    union { __nv_bfloat16 h[4]; uint2 u; } H, L;
    float xs[4] = {x.x, x.y, x.z, x.w};
#pragma unroll
    for (int j = 0; j < 4; j++) {
        H.h[j] = __float2bfloat16(xs[j]);
        L.h[j] = __float2bfloat16(xs[j] - __bfloat162float(H.h[j]));
    }
    Hu = H.u; Lu = L.u;
}

// inputs q,k,v -> A' layout [hi | lo | hi]
__global__ __launch_bounds__(256) void conv_split3(
    const float* __restrict__ q, const float* __restrict__ k, const float* __restrict__ v)
{
    const float* src = (blockIdx.z == 0) ? q : (blockIdx.z == 1) ? k : v;
    __nv_bfloat16* dst = (blockIdx.z == 0) ? g_A2q : (blockIdx.z == 1) ? g_A2k : g_A2v;
    const int i4 = blockIdx.x*256 + threadIdx.x;          // < 262144
    const float4 x = reinterpret_cast<const float4*>(src)[i4];
    const int row = i4 >> 6, c4 = (i4 & 63) << 2;
    uint2 Hu, Lu; split4(x, Hu, Lu);
    *reinterpret_cast<uint2*>(&dst[(size_t)row*KTOT + c4])       = Hu;
    *reinterpret_cast<uint2*>(&dst[(size_t)row*KTOT + 256 + c4]) = Lu;
    *reinterpret_cast<uint2*>(&dst[(size_t)row*KTOT + 512 + c4]) = Hu;
}

// weights -> B' layout [hi | hi | lo]   (pairs with A's [hi | lo | hi])
__global__ __launch_bounds__(256) void conv_splitW(
    const float* __restrict__ Wq, const float* __restrict__ Wk,
    const float* __restrict__ Wv, const float* __restrict__ W0)
{
    const float* src = (blockIdx.z == 0) ? Wq : (blockIdx.z == 1) ? Wk :
                       (blockIdx.z == 2) ? Wv : W0;
    __nv_bfloat16* dst = g_B2 + (size_t)blockIdx.z * WSZ;
    const int i4 = blockIdx.x*256 + threadIdx.x;          // < 16384
    const float4 x = reinterpret_cast<const float4*>(src)[i4];
    const int row = i4 >> 6, c4 = (i4 & 63) << 2;
    uint2 Hu, Lu; split4(x, Hu, Lu);
    *reinterpret_cast<uint2*>(&dst[(size_t)row*KTOT + c4])       = Hu;
    *reinterpret_cast<uint2*>(&dst[(size_t)row*KTOT + 256 + c4]) = Hu;
    *reinterpret_cast<uint2*>(&dst[(size_t)row*KTOT + 512 + c4]) = Lu;
}

// ============================================================================
// bf16 tensor-core GEMM: C[M,256] = A'[M,768] . B'[N,768]^T + bias
//   BM=128 BN=64 BK=32, 256 threads (8 warps, 4x2), warp tile 32x32
// ============================================================================
#define LDMX4(R, addr) \
    asm volatile("ldmatrix.sync.aligned.m8n8.x4.shared.b16 {%0,%1,%2,%3}, [%4];" \
        : "=r"((R)[0]), "=r"((R)[1]), "=r"((R)[2]), "=r"((R)[3]) : "r"(addr))

#define MMA16816(C, A, B0, B1) \
    asm volatile("mma.sync.aligned.m16n8k16.row.col.f32.bf16.bf16.f32 " \
        "{%0,%1,%2,%3},{%4,%5,%6,%7},{%8,%9},{%0,%1,%2,%3};" \
        : "+f"((C)[0]), "+f"((C)[1]), "+f"((C)[2]), "+f"((C)[3]) \
        : "r"((A)[0]), "r"((A)[1]), "r"((A)[2]), "r"((A)[3]), "r"(B0), "r"(B1))

__device__ __forceinline__ void mma_gemm_body(
    const __nv_bfloat16* __restrict__ A, const __nv_bfloat16* __restrict__ B,
    const float* __restrict__ bias, float* __restrict__ C)
{
    __shared__ __align__(16) __nv_bfloat16 As[128*40];
    __shared__ __align__(16) __nv_bfloat16 Bs[64*40];
    const int tid = threadIdx.x;
    const int m0 = blockIdx.x*128, n0 = blockIdx.y*64;
    const int w = tid >> 5, lane = tid & 31;
    const int wm = (w >> 1) * 32, wn = (w & 1) * 32;

    float acc[2][4][4];
#pragma unroll
    for (int a = 0; a < 2; a++)
#pragma unroll
        for (int j = 0; j < 4; j++)
#pragma unroll
            for (int e = 0; e < 4; e++) acc[a][j][e] = 0.f;

    // ldmatrix smem offsets (bf16 element units)
    const int a_row = (lane & 15), a_c8 = (lane >> 4) << 3;
    const int b_row = (lane & 7) + ((lane >> 4) << 3), b_c8 = ((lane >> 3) & 1) << 3;

    for (int kt = 0; kt < KTOT; kt += 32) {
        {
            int id = tid;
#pragma unroll
            for (int r = 0; r < 2; r++, id += 256) {
                const int row = id >> 2, c8 = (id & 3) << 3;
                *reinterpret_cast<uint4*>(&As[row*40 + c8]) =
                    *reinterpret_cast<const uint4*>(&A[(size_t)(m0+row)*KTOT + kt + c8]);
            }
            const int row = tid >> 2, c8 = (tid & 3) << 3;
            *reinterpret_cast<uint4*>(&Bs[row*40 + c8]) =
                *reinterpret_cast<const uint4*>(&B[(size_t)(n0+row)*KTOT + kt + c8]);
        }
        __syncthreads();
#pragma unroll
        for (int kk = 0; kk < 32; kk += 16) {
            uint32_t afr[2][4], bfr[2][4];
#pragma unroll
            for (int am = 0; am < 2; am++) {
                uint32_t ad = (uint32_t)__cvta_generic_to_shared(
                    &As[(wm + am*16 + a_row)*40 + kk + a_c8]);
                LDMX4(afr[am], ad);
            }
#pragma unroll
            for (int bn = 0; bn < 2; bn++) {
                uint32_t ad = (uint32_t)__cvta_generic_to_shared(
                    &Bs[(wn + bn*16 + b_row)*40 + kk + b_c8]);
                LDMX4(bfr[bn], ad);
            }
#pragma unroll
            for (int am = 0; am < 2; am++)
#pragma unroll
                for (int j = 0; j < 4; j++)
                    MMA16816(acc[am][j], afr[am],
                             bfr[j >> 1][(j & 1)*2], bfr[j >> 1][(j & 1)*2 + 1]);
        }
        __syncthreads();
    }

    const int r = lane >> 2, cp = (lane & 3) * 2;
#pragma unroll
    for (int am = 0; am < 2; am++)
#pragma unroll
        for (int j = 0; j < 4; j++) {
            const int col = n0 + wn + j*8 + cp;
            const float bb0 = bias[col], bb1 = bias[col+1];
            const int row0 = m0 + wm + am*16 + r;
            *reinterpret_cast<float2*>(&C[(size_t)row0*256 + col]) =
                make_float2(acc[am][j][0] + bb0, acc[am][j][1] + bb1);
            *reinterpret_cast<float2*>(&C[(size_t)(row0+8)*256 + col]) =
                make_float2(acc[am][j][2] + bb0, acc[am][j][3] + bb1);
        }
}

__global__ __launch_bounds__(256) void proj_mma(
    const float* __restrict__ bq, const float* __restrict__ bk, const float* __restrict__ bv)
{
    if (blockIdx.z == 0)      mma_gemm_body(g_A2q, g_B2,         bq, g_Qp);
    else if (blockIdx.z == 1) mma_gemm_body(g_A2k, g_B2 +   WSZ, bk, g_Kp);
    else                      mma_gemm_body(g_A2v, g_B2 + 2*WSZ, bv, g_Vp);
}

__global__ __launch_bounds__(256) void final_mma(const float* __restrict__ b0,
                                                 float* __restrict__ out)
{
    mma_gemm_body(g_X2, g_B2 + 3*WSZ, b0, out);
}

// ============================================================================
// Prefix scans along seq (per b,h,d)
// ============================================================================
__global__ void scan_chunks()
{
    const int chunk = blockIdx.x, bh = blockIdx.y;
    const int b = bh >> 3, h = bh & 7;
    const int d = threadIdx.x;
    const float* src; float* dst; float* ctot;
    if (blockIdx.z == 0) { src = g_Kp; dst = g_Kpre; ctot = g_ctotK; }
    else                 { src = g_Vp; dst = g_Vpre; ctot = g_ctotV; }
    const size_t base = ((size_t)(b*SEQ + chunk*CHUNK))*D_MODEL + h*DH + d;
    float acc = 0.f;
    for (int i = 0; i < CHUNK; i += 8) {
        float t[8];
#pragma unroll
        for (int j = 0; j < 8; j++) t[j] = src[base + (size_t)(i+j)*D_MODEL];
#pragma unroll
        for (int j = 0; j < 8; j++) { acc += t[j]; dst[base + (size_t)(i+j)*D_MODEL] = acc; }
    }
    ctot[(bh*NCHUNK + chunk)*DH + d] = acc;
}

__global__ void scan_offsets()
{
    const int bh = blockIdx.x, d = threadIdx.x;
    const float* ctot = (blockIdx.y == 0) ? g_ctotK : g_ctotV;
    float*       off  = (blockIdx.y == 0) ? g_koff  : g_voff;
    float acc = 0.f;
    for (int c = 0; c < NCHUNK; c++) {
        off[(bh*(NCHUNK+1)+c)*DH + d] = acc;
        acc += ctot[(bh*NCHUNK+c)*DH + d];
    }
    off[(bh*(NCHUNK+1)+NCHUNK)*DH + d] = acc;
}

// ============================================================================
// K^T V: warp-private register outer products, 128 partial slabs, then reduce
// ============================================================================
__global__ __launch_bounds__(256) void ktv_partial()
{
    const int chunk = blockIdx.x, bh = blockIdx.y;
    const int b = bh >> 3, h = bh & 7;
    __shared__ float Vsm[128][32];
    const int tid = threadIdx.x, w = tid >> 5, lane = tid & 31;
    for (int i = tid; i < 128*32; i += 256) {
        const int row = i >> 5, d = i & 31;
        Vsm[row][d] = g_Vp[((size_t)(b*SEQ + chunk*CHUNK + row))*D_MODEL + h*DH + d];
    }
    __syncthreads();
    float acc[32];
#pragma unroll
    for (int d = 0; d < 32; d++) acc[d] = 0.f;
    const int r0 = w*16;
    for (int r = 0; r < 16; r++) {
        const float kreg = g_Kp[((size_t)(b*SEQ + chunk*CHUNK + r0 + r))*D_MODEL + h*DH + lane];
#pragma unroll
        for (int d = 0; d < 32; d++) acc[d] += kreg * Vsm[r0 + r][d];
    }
    float* p = &g_ktvp[(((size_t)chunk*8 + w)*BHN + bh)*DH*DH + lane*DH];
#pragma unroll
    for (int d = 0; d < 32; d += 4)
        *reinterpret_cast<float4*>(&p[d]) = make_float4(acc[d], acc[d+1], acc[d+2], acc[d+3]);
}

__global__ void ktv_reduce()   // grid 64, block 256
{
    const int bh = blockIdx.x >> 2;
    const int i  = (blockIdx.x & 3)*256 + threadIdx.x;   // 0..1023
    float s = 0.f;
    for (int sl = 0; sl < 128; sl++) s += g_ktvp[((size_t)sl*BHN + bh)*DH*DH + i];
    g_ktv[bh*DH*DH + i] = s;
}

// ============================================================================
// Stage 3: content via KtV + relative band/prefix; epilogue writes split-bf16 X'
// ============================================================================
__global__ __launch_bounds__(256) void stage3(const float* __restrict__ tk,
                                              const float* __restrict__ tv)
{
    const int bh = blockIdx.y;
    const int b = bh >> 3, h = bh & 7;
    const int q0 = blockIdx.x * QT;

    __shared__ float Ksm[(QT+2*MAXREL)*33];
    __shared__ float Vsm[(QT+2*MAXREL)*32];
    __shared__ float KtVs[DH*DH];
    __shared__ float Tks[NT*33];
    __shared__ float Tvs[NT*32];

    const int tid = threadIdx.x;
    for (int i = tid; i < (QT+2*MAXREL)*DH; i += 256) {
        const int row = i >> 5, d = i & 31;
        const int kidx = q0 - MAXREL + row;
        float kv = 0.f, vv = 0.f;
        if (kidx >= 0 && kidx < SEQ) {
            const size_t gi = ((size_t)(b*SEQ + kidx))*D_MODEL + h*DH + d;
            kv = g_Kp[gi]; vv = g_Vp[gi];
        }
        Ksm[row*33 + d] = kv;
        Vsm[row*32 + d] = vv;
    }
    for (int i = tid; i < DH*DH; i += 256) KtVs[i] = g_ktv[bh*DH*DH + i];
    for (int i = tid; i < NT*DH; i += 256) {
        const int t = i >> 5, e = i & 31;
        Tks[t*33 + e] = tk[i];
        Tvs[i]        = tv[i];
    }
    __syncthreads();

    const int w = tid >> 5, lane = tid & 31;
    const float ktotL = g_koff[(bh*(NCHUNK+1)+NCHUNK)*DH + lane];
    const float vtotL = g_voff[(bh*(NCHUNK+1)+NCHUNK)*DH + lane];

    for (int iq = 0; iq < QT/8; iq++) {
        const int q = q0 + iq*8 + w;
        const float qreg = g_Qp[((size_t)(b*SEQ + q))*D_MODEL + h*DH + lane];

        float kpreL = 0.f, vpreL = 0.f, ksufL = 0.f, vsufL = 0.f;
        const int r1 = q - MAXREL;
        if (r1 >= 0) {
            const size_t gi = ((size_t)(b*SEQ + r1))*D_MODEL + h*DH + lane;
            const int c = r1 >> 7;
            kpreL = g_Kpre[gi] + g_koff[(bh*(NCHUNK+1)+c)*DH + lane];
            vpreL = g_Vpre[gi] + g_voff[(bh*(NCHUNK+1)+c)*DH + lane];
        }
        const bool hasR = (q + MAXREL) <= SEQ-1;
        if (hasR) {
            const int r2 = q + MAXREL - 1;
            const size_t gi = ((size_t)(b*SEQ + r2))*D_MODEL + h*DH + lane;
            const int c = r2 >> 7;
            ksufL = ktotL - (g_Kpre[gi] + g_koff[(bh*(NCHUNK+1)+c)*DH + lane]);
            vsufL = vtotL - (g_Vpre[gi] + g_voff[(bh*(NCHUNK+1)+c)*DH + lane]);
        }

        const int tmin = (lane < NT-1) ? lane : NT-1;
        const float* krow = &Ksm[(q - q0 + tmin)*33];
        const float* tkr  = &Tks[tmin*33];
        float acc_s = 0.f, acc_int = 0.f, acc_ktv = 0.f;
        float pp = qreg * kpreL;
        float ss = qreg * ksufL;
#pragma unroll
        for (int e = 0; e < 32; e++) {
            const float qe = __shfl_sync(0xffffffffu, qreg, e);
            acc_s   += qe * tkr[e];
            acc_int += qe * krow[e];
            acc_ktv += qe * KtVs[e*DH + lane];
        }
#pragma unroll
        for (int off = 16; off > 0; off >>= 1) {
            pp += __shfl_xor_sync(0xffffffffu, pp, off);
            ss += __shfl_xor_sync(0xffffffffu, ss, off);
        }

        float Sval;
        if (lane == 0) {
            Sval = (r1 >= 0) ? (pp + (float)(q - MAXREL + 1) * acc_s) : 0.f;
        } else if (lane == NT-1) {
            Sval = hasR ? (ss + (float)(SEQ - q - MAXREL) * acc_s) : 0.f;
        } else if (lane < NT-1) {
            const int kk = q + lane - MAXREL;
            Sval = (kk >= 0 && kk < SEQ) ? (acc_int + acc_s) : 0.f;
        } else {
            Sval = 0.f;
        }

        const float s0  = __shfl_sync(0xffffffffu, acc_s, 0);
        const float s20 = __shfl_sync(0xffffffffu, acc_s, NT-1);
        float wv = acc_ktv + s0*vpreL + s20*vsufL;
        const int base = q - q0;
#pragma unroll
        for (int t = 1; t < NT-1; t++) {
            const float st = __shfl_sync(0xffffffffu, acc_s, t);
            const int kk = q + t - MAXREL;
            if (kk >= 0 && kk < SEQ)
                wv += st * Vsm[(base+t)*32 + lane];
        }
#pragma unroll
        for (int t = 0; t < NT; t++) {
            const float sv = __shfl_sync(0xffffffffu, Sval, t);
            wv += sv * Tvs[t*32 + lane];
        }

        // epilogue: split-bf16 write of X' row (A-operand layout [hi|lo|hi])
        const float o = wv * INV_SCALE;
        const __nv_bfloat16 hi = __float2bfloat16(o);
        const __nv_bfloat16 lo = __float2bfloat16(o - __bfloat162float(hi));
        const size_t rb = ((size_t)(b*SEQ + q))*KTOT + h*DH + lane;
        g_X2[rb]       = hi;
        g_X2[rb + 256] = lo;
        g_X2[rb + 512] = hi;
    }
}

// ============================================================================
// launch
// ============================================================================
extern "C" void kernel_launch(void* const* d_in, const int* in_sizes, int n_in,
                              void* d_out, int out_size)
{
    const float* q   = (const float*)d_in[0];
    const float* k   = (const float*)d_in[1];
    const float* v   = (const float*)d_in[2];
    const float* Wq  = (const float*)d_in[4];
    const float* bq  = (const float*)d_in[5];
    const float* Wk  = (const float*)d_in[6];
    const float* bk  = (const float*)d_in[7];
    const float* Wv  = (const float*)d_in[8];
    const float* bv  = (const float*)d_in[9];
    const float* W0  = (const float*)d_in[10];
    const float* b0  = (const float*)d_in[11];
    const float* tk  = (const float*)d_in[12];
    const float* tv  = (const float*)d_in[13];
    float* out = (float*)d_out;

    conv_split3<<<dim3(1024, 1, 3), 256>>>(q, k, v);
    conv_splitW<<<dim3(64, 1, 4), 256>>>(Wq, Wk, Wv, W0);
    proj_mma   <<<dim3(MROWS/128, D_MODEL/64, 3), 256>>>(bq, bk, bv);
    scan_chunks<<<dim3(NCHUNK, BHN, 2), 32>>>();
    scan_offsets<<<dim3(BHN, 2), 32>>>();
    ktv_partial<<<dim3(NCHUNK, BHN), 256>>>();
    ktv_reduce <<<64, 256>>>();
    stage3     <<<dim3(SEQ/QT, BHN), 256>>>(tk, tv);
    final_mma  <<<dim3(MROWS/128, D_MODEL/64), 256>>>(b0, out);
}

// round 3
// speedup vs baseline: 1.1448x; 1.0327x over previous
#include <cuda_runtime.h>
#include <cuda_bf16.h>
#include <cstdint>

// ============================================================================
// Relative-position MHA (NO softmax) — algebraic restructure, fused conversions.
//   GEMMs: split-bf16 (3-term) mma.sync, K'=768, fp32->bf16 fused in tile load
//   content path:  Q (K^T V)
//   relative path: 21-bucket band + in-block incremental prefix/suffix sums
// ============================================================================

#define D_MODEL 256
#define HEADS   8
#define DH      32
#define SEQ     2048
#define BATCH   2
#define MAXREL  10
#define NT      21
#define BHN     (BATCH*HEADS)       // 16
#define MROWS   (BATCH*SEQ)         // 4096
#define NCHUNK  16                  // 128-row chunks
#define QT      128
#define INV_SCALE (1.0f/16.0f)
#define KTOT 768                    // split-bf16: A=[hi|lo|hi], B=[hi|hi|lo]

// -------------------- scratch (device globals; no allocs) -------------------
__device__ float g_Qp[MROWS*D_MODEL];
__device__ float g_Kp[MROWS*D_MODEL];
__device__ float g_Vp[MROWS*D_MODEL];
__device__ __align__(16) __nv_bfloat16 g_X2[MROWS*KTOT];      // stage3 output, split layout
__device__ float g_csumK[BHN*NCHUNK*DH];                      // per-chunk column sums
__device__ float g_csumV[BHN*NCHUNK*DH];
__device__ float g_koff[BHN*(NCHUNK+1)*DH];                   // exclusive offsets + total
__device__ float g_voff[BHN*(NCHUNK+1)*DH];
__device__ __align__(16) float g_ktvp[128*BHN*DH*DH];         // K^T V partial slabs
__device__ float g_ktv[BHN*DH*DH];

// ============================================================================
// helpers
// ============================================================================
__device__ __forceinline__ uint2 cvt4(const float4 x, bool lo_part)
{
    union { __nv_bfloat16 h[4]; uint2 u; } r;
    float xs[4] = {x.x, x.y, x.z, x.w};
#pragma unroll
    for (int j = 0; j < 4; j++) {
        __nv_bfloat16 hi = __float2bfloat16(xs[j]);
        r.h[j] = lo_part ? __float2bfloat16(xs[j] - __bfloat162float(hi)) : hi;
    }
    return r.u;
}

#define LDMX4(R, addr) \
    asm volatile("ldmatrix.sync.aligned.m8n8.x4.shared.b16 {%0,%1,%2,%3}, [%4];" \
        : "=r"((R)[0]), "=r"((R)[1]), "=r"((R)[2]), "=r"((R)[3]) : "r"(addr))

#define MMA16816(C, A, B0, B1) \
    asm volatile("mma.sync.aligned.m16n8k16.row.col.f32.bf16.bf16.f32 " \
        "{%0,%1,%2,%3},{%4,%5,%6,%7},{%8,%9},{%0,%1,%2,%3};" \
        : "+f"((C)[0]), "+f"((C)[1]), "+f"((C)[2]), "+f"((C)[3]) \
        : "r"((A)[0]), "r"((A)[1]), "r"((A)[2]), "r"((A)[3]), "r"(B0), "r"(B1))

// ============================================================================
// bf16 tensor-core GEMM: C[M,256] = split(A) . split(W)^T + bias
//   A either fp32 [M,256] (converted on load) or prebuilt bf16 [M,768]
//   W always fp32 [256,256], parts [hi|hi|lo]; A parts [hi|lo|hi]
//   BM=128 BN=64 BK=32, 256 threads (8 warps 4x2), warp tile 32x32
// ============================================================================
template<bool AFP32>
__device__ __forceinline__ void mma_gemm_body(
    const void* __restrict__ Aptr, const float* __restrict__ W,
    const float* __restrict__ bias, float* __restrict__ C)
{
    __shared__ __align__(16) __nv_bfloat16 As[128*40];
    __shared__ __align__(16) __nv_bfloat16 Bs[64*40];
    const int tid = threadIdx.x;
    const int m0 = blockIdx.x*128, n0 = blockIdx.y*64;
    const int w = tid >> 5, lane = tid & 31;
    const int wm = (w >> 1) * 32, wn = (w & 1) * 32;

    float acc[2][4][4];
#pragma unroll
    for (int a = 0; a < 2; a++)
#pragma unroll
        for (int j = 0; j < 4; j++)
#pragma unroll
            for (int e = 0; e < 4; e++) acc[a][j][e] = 0.f;

    const int a_row = (lane & 15), a_c8 = (lane >> 4) << 3;
    const int b_row = (lane & 7) + ((lane >> 4) << 3), b_c8 = ((lane >> 3) & 1) << 3;

    for (int kt = 0; kt < KTOT; kt += 32) {
        const int part = kt >> 8, sc = kt & 255;
        // ---- A tile 128x32
        if (AFP32) {
            const float* A = (const float*)Aptr;
            const bool aLo = (part == 1);
#pragma unroll
            for (int r = 0; r < 4; r++) {
                const int id = tid + r*256;            // 0..1023
                const int row = id >> 3, c4 = (id & 7) << 2;
                const float4 av = *reinterpret_cast<const float4*>(
                    &A[(size_t)(m0+row)*256 + sc + c4]);
                *reinterpret_cast<uint2*>(&As[row*40 + c4]) = cvt4(av, aLo);
            }
        } else {
            const __nv_bfloat16* A = (const __nv_bfloat16*)Aptr;
#pragma unroll
            for (int r = 0; r < 2; r++) {
                const int id = tid + r*256;            // 0..511
                const int row = id >> 2, c8 = (id & 3) << 3;
                *reinterpret_cast<uint4*>(&As[row*40 + c8]) =
                    *reinterpret_cast<const uint4*>(&A[(size_t)(m0+row)*KTOT + kt + c8]);
            }
        }
        // ---- B tile 64x32 (fp32 W, convert)
        {
            const bool bLo = (part == 2);
#pragma unroll
            for (int r = 0; r < 2; r++) {
                const int id = tid + r*256;            // 0..511
                const int row = id >> 3, c4 = (id & 7) << 2;
                const float4 wv = *reinterpret_cast<const float4*>(
                    &W[(size_t)(n0+row)*256 + sc + c4]);
                *reinterpret_cast<uint2*>(&Bs[row*40 + c4]) = cvt4(wv, bLo);
            }
        }
        __syncthreads();
#pragma unroll
        for (int kk = 0; kk < 32; kk += 16) {
            uint32_t afr[2][4], bfr[2][4];
#pragma unroll
            for (int am = 0; am < 2; am++) {
                uint32_t ad = (uint32_t)__cvta_generic_to_shared(
                    &As[(wm + am*16 + a_row)*40 + kk + a_c8]);
                LDMX4(afr[am], ad);
            }
#pragma unroll
            for (int bn = 0; bn < 2; bn++) {
                uint32_t ad = (uint32_t)__cvta_generic_to_shared(
                    &Bs[(wn + bn*16 + b_row)*40 + kk + b_c8]);
                LDMX4(bfr[bn], ad);
            }
#pragma unroll
            for (int am = 0; am < 2; am++)
#pragma unroll
                for (int j = 0; j < 4; j++)
                    MMA16816(acc[am][j], afr[am],
                             bfr[j >> 1][(j & 1)*2], bfr[j >> 1][(j & 1)*2 + 1]);
        }
        __syncthreads();
    }

    const int r = lane >> 2, cp = (lane & 3) * 2;
#pragma unroll
    for (int am = 0; am < 2; am++)
#pragma unroll
        for (int j = 0; j < 4; j++) {
            const int col = n0 + wn + j*8 + cp;
            const float bb0 = bias[col], bb1 = bias[col+1];
            const int row0 = m0 + wm + am*16 + r;
            *reinterpret_cast<float2*>(&C[(size_t)row0*256 + col]) =
                make_float2(acc[am][j][0] + bb0, acc[am][j][1] + bb1);
            *reinterpret_cast<float2*>(&C[(size_t)(row0+8)*256 + col]) =
                make_float2(acc[am][j][2] + bb0, acc[am][j][3] + bb1);
        }
}

__global__ __launch_bounds__(256) void proj_mma(
    const float* __restrict__ q,  const float* __restrict__ k,  const float* __restrict__ v,
    const float* __restrict__ Wq, const float* __restrict__ bq,
    const float* __restrict__ Wk, const float* __restrict__ bk,
    const float* __restrict__ Wv, const float* __restrict__ bv)
{
    if (blockIdx.z == 0)      mma_gemm_body<true>(q, Wq, bq, g_Qp);
    else if (blockIdx.z == 1) mma_gemm_body<true>(k, Wk, bk, g_Kp);
    else                      mma_gemm_body<true>(v, Wv, bv, g_Vp);
}

__global__ __launch_bounds__(256) void final_mma(
    const float* __restrict__ W0, const float* __restrict__ b0, float* __restrict__ out)
{
    mma_gemm_body<false>(g_X2, W0, b0, out);
}

// ============================================================================
// K^T V partials + per-chunk column sums (fused). Block = (chunk, bh).
// ============================================================================
__global__ __launch_bounds__(256) void ktv_partial()
{
    const int chunk = blockIdx.x, bh = blockIdx.y;
    const int b = bh >> 3, h = bh & 7;
    __shared__ float Vsm[128][32];
    __shared__ float redK[8][32], redV[8][32];
    const int tid = threadIdx.x, w = tid >> 5, lane = tid & 31;
    for (int i = tid; i < 128*32; i += 256) {
        const int row = i >> 5, d = i & 31;
        Vsm[row][d] = g_Vp[((size_t)(b*SEQ + chunk*128 + row))*D_MODEL + h*DH + d];
    }
    __syncthreads();
    float acc[32];
#pragma unroll
    for (int d = 0; d < 32; d++) acc[d] = 0.f;
    float ksum = 0.f, vsum = 0.f;
    const int r0 = w*16;
    for (int r = 0; r < 16; r++) {
        const float kreg = g_Kp[((size_t)(b*SEQ + chunk*128 + r0 + r))*D_MODEL + h*DH + lane];
        ksum += kreg;
        vsum += Vsm[r0 + r][lane];
#pragma unroll
        for (int d = 0; d < 32; d++) acc[d] += kreg * Vsm[r0 + r][d];
    }
    float* p = &g_ktvp[(((size_t)chunk*8 + w)*BHN + bh)*DH*DH + lane*DH];
#pragma unroll
    for (int d = 0; d < 32; d += 4)
        *reinterpret_cast<float4*>(&p[d]) = make_float4(acc[d], acc[d+1], acc[d+2], acc[d+3]);
    redK[w][lane] = ksum;
    redV[w][lane] = vsum;
    __syncthreads();
    if (w == 0) {
        float sk = 0.f, sv = 0.f;
#pragma unroll
        for (int i = 0; i < 8; i++) { sk += redK[i][lane]; sv += redV[i][lane]; }
        g_csumK[(bh*NCHUNK + chunk)*DH + lane] = sk;
        g_csumV[(bh*NCHUNK + chunk)*DH + lane] = sv;
    }
}

// ============================================================================
// Combined: ktv reduce (blocks 0..63) + chunk-offset scans (blocks 64..95)
// ============================================================================
__global__ __launch_bounds__(256) void combo_reduce()
{
    if (blockIdx.x < 64) {
        const int bh = blockIdx.x >> 2;
        const int i  = (blockIdx.x & 3)*256 + threadIdx.x;   // 0..1023
        float s = 0.f;
        for (int sl = 0; sl < 128; sl++) s += g_ktvp[((size_t)sl*BHN + bh)*DH*DH + i];
        g_ktv[bh*DH*DH + i] = s;
    } else {
        const int bid = blockIdx.x - 64;                     // 0..31
        const int bh = bid >> 1;
        const float* cs = (bid & 1) ? g_csumV : g_csumK;
        float*       off = (bid & 1) ? g_voff  : g_koff;
        if (threadIdx.x < 32) {
            const int d = threadIdx.x;
            float a = 0.f;
            for (int c = 0; c < NCHUNK; c++) {
                off[(bh*(NCHUNK+1)+c)*DH + d] = a;
                a += cs[(bh*NCHUNK+c)*DH + d];
            }
            off[(bh*(NCHUNK+1)+NCHUNK)*DH + d] = a;
        }
    }
}

// ============================================================================
// Stage 3: content via KtV + relative band; prefixes maintained incrementally
// from the smem window. Epilogue writes split-bf16 X'.
// ============================================================================
__global__ __launch_bounds__(256) void stage3(const float* __restrict__ tk,
                                              const float* __restrict__ tv)
{
    const int bh = blockIdx.y;
    const int b = bh >> 3, h = bh & 7;
    const int q0 = blockIdx.x * QT;

    __shared__ float Ksm[(QT+2*MAXREL)*33];   // window rows q0-10 .. q0+137
    __shared__ float Vsm[(QT+2*MAXREL)*32];
    __shared__ float KtVs[DH*DH];
    __shared__ float Tks[NT*33];
    __shared__ float Tvs[NT*32];

    const int tid = threadIdx.x;
    for (int i = tid; i < (QT+2*MAXREL)*DH; i += 256) {
        const int row = i >> 5, d = i & 31;
        const int kidx = q0 - MAXREL + row;
        float kv = 0.f, vv = 0.f;
        if (kidx >= 0 && kidx < SEQ) {
            const size_t gi = ((size_t)(b*SEQ + kidx))*D_MODEL + h*DH + d;
            kv = g_Kp[gi]; vv = g_Vp[gi];
        }
        Ksm[row*33 + d] = kv;
        Vsm[row*32 + d] = vv;
    }
    for (int i = tid; i < DH*DH; i += 256) KtVs[i] = g_ktv[bh*DH*DH + i];
    for (int i = tid; i < NT*DH; i += 256) {
        const int t = i >> 5, e = i & 31;
        Tks[t*33 + e] = tk[i];
        Tvs[i]        = tv[i];
    }
    __syncthreads();

    const int w = tid >> 5, lane = tid & 31;
    const float ktotL = g_koff[(bh*(NCHUNK+1)+NCHUNK)*DH + lane];
    const float vtotL = g_voff[(bh*(NCHUNK+1)+NCHUNK)*DH + lane];
    const float offK  = g_koff[(bh*(NCHUNK+1)+(q0>>7))*DH + lane];
    const float offV  = g_voff[(bh*(NCHUNK+1)+(q0>>7))*DH + lane];

    // incremental inclusive prefixes: k1/v1 through row q-10, k2/v2 through q+9
    float L10k = 0.f, L10v = 0.f;
#pragma unroll
    for (int j = 0; j < 10; j++) { L10k += Ksm[j*33+lane]; L10v += Vsm[j*32+lane]; }
    float k1 = offK - L10k, v1 = offV - L10v;
    for (int j = 0; j <= w; j++) { k1 += Ksm[j*33+lane]; v1 += Vsm[j*32+lane]; }
    float k2 = k1, v2 = v1;
#pragma unroll
    for (int j = 1; j <= 19; j++) {
        k2 += Ksm[(w+j)*33+lane]; v2 += Vsm[(w+j)*32+lane];
    }
    int jp = w;   // window row included in k1; k2 includes through jp+19

    for (int iq = 0; iq < QT/8; iq++) {
        if (iq > 0) {
#pragma unroll
            for (int t = 1; t <= 8; t++) {
                k1 += Ksm[(jp+t)*33+lane];    v1 += Vsm[(jp+t)*32+lane];
                k2 += Ksm[(jp+19+t)*33+lane]; v2 += Vsm[(jp+19+t)*32+lane];
            }
            jp += 8;
        }
        const int q = q0 + iq*8 + w;
        const float qreg = g_Qp[((size_t)(b*SEQ + q))*D_MODEL + h*DH + lane];

        const float kpreL = k1, vpreL = v1;
        const float ksufL = ktotL - k2, vsufL = vtotL - v2;
        const int r1 = q - MAXREL;
        const bool hasR = (q + MAXREL) <= SEQ-1;

        const int tmin = (lane < NT-1) ? lane : NT-1;
        const float* krow = &Ksm[(q - q0 + tmin)*33];
        const float* tkr  = &Tks[tmin*33];
        float acc_s = 0.f, acc_int = 0.f, acc_ktv = 0.f;
        float pp = qreg * kpreL;
        float ss = qreg * ksufL;
#pragma unroll
        for (int e = 0; e < 32; e++) {
            const float qe = __shfl_sync(0xffffffffu, qreg, e);
            acc_s   += qe * tkr[e];
            acc_int += qe * krow[e];
            acc_ktv += qe * KtVs[e*DH + lane];
        }
#pragma unroll
        for (int off = 16; off > 0; off >>= 1) {
            pp += __shfl_xor_sync(0xffffffffu, pp, off);
            ss += __shfl_xor_sync(0xffffffffu, ss, off);
        }

        float Sval;
        if (lane == 0) {
            Sval = (r1 >= 0) ? (pp + (float)(q - MAXREL + 1) * acc_s) : 0.f;
        } else if (lane == NT-1) {
            Sval = hasR ? (ss + (float)(SEQ - q - MAXREL) * acc_s) : 0.f;
        } else if (lane < NT-1) {
            const int kk = q + lane - MAXREL;
            Sval = (kk >= 0 && kk < SEQ) ? (acc_int + acc_s) : 0.f;
        } else {
            Sval = 0.f;
        }

        const float s0  = __shfl_sync(0xffffffffu, acc_s, 0);
        const float s20 = __shfl_sync(0xffffffffu, acc_s, NT-1);
        float wv = acc_ktv + s0*vpreL + s20*vsufL;
        const int base = q - q0;
#pragma unroll
        for (int t = 1; t < NT-1; t++) {
            const float st = __shfl_sync(0xffffffffu, acc_s, t);
            const int kk = q + t - MAXREL;
            if (kk >= 0 && kk < SEQ)
                wv += st * Vsm[(base+t)*32 + lane];
        }
#pragma unroll
        for (int t = 0; t < NT; t++) {
            const float sv = __shfl_sync(0xffffffffu, Sval, t);
            wv += sv * Tvs[t*32 + lane];
        }

        // epilogue: split-bf16 write of X' row ([hi|lo|hi])
        const float o = wv * INV_SCALE;
        const __nv_bfloat16 hi = __float2bfloat16(o);
        const __nv_bfloat16 lo = __float2bfloat16(o - __bfloat162float(hi));
        const size_t rb = ((size_t)(b*SEQ + q))*KTOT + h*DH + lane;
        g_X2[rb]       = hi;
        g_X2[rb + 256] = lo;
        g_X2[rb + 512] = hi;
    }
}

// ============================================================================
// launch
// ============================================================================
extern "C" void kernel_launch(void* const* d_in, const int* in_sizes, int n_in,
                              void* d_out, int out_size)
{
    const float* q   = (const float*)d_in[0];
    const float* k   = (const float*)d_in[1];
    const float* v   = (const float*)d_in[2];
    const float* Wq  = (const float*)d_in[4];
    const float* bq  = (const float*)d_in[5];
    const float* Wk  = (const float*)d_in[6];
    const float* bk  = (const float*)d_in[7];
    const float* Wv  = (const float*)d_in[8];
    const float* bv  = (const float*)d_in[9];
    const float* W0  = (const float*)d_in[10];
    const float* b0  = (const float*)d_in[11];
    const float* tk  = (const float*)d_in[12];
    const float* tv  = (const float*)d_in[13];
    float* out = (float*)d_out;

    proj_mma   <<<dim3(MROWS/128, D_MODEL/64, 3), 256>>>(q, k, v, Wq, bq, Wk, bk, Wv, bv);
    ktv_partial<<<dim3(NCHUNK, BHN), 256>>>();
    combo_reduce<<<96, 256>>>();
    stage3     <<<dim3(SEQ/QT, BHN), 256>>>(tk, tv);
    final_mma  <<<dim3(MROWS/128, D_MODEL/64), 256>>>(W0, b0, out);
}